// round 16
// baseline (speedup 1.0000x reference)
#include <cuda_runtime.h>
#include <cuda_bf16.h>
#include <mma.h>
#include <cstdint>

using namespace nvcuda;

#define HH 128
#define WW 128
#define HWN 16384
#define BHW (4 * 16384)
#define BN 4
#define CN 64

typedef unsigned long long ull;

__device__ __constant__ int c_RATES[4] = {2, 3, 5, 9};

// Scratch (static device globals: allocation-free, graph-capturable)
__device__ float g_xhwc[BN * HWN * CN];             // [b][p][c] f32
__device__ __nv_bfloat16 g_xbf_hi[BN * HWN * CN];   // [b][p][c] bf16 hi
__device__ __nv_bfloat16 g_xbf_lo[BN * HWN * CN];   // [b][p][c] bf16 lo residual
__device__ float g_off[4 * 18 * BHW];               // [j][k2][b*HW+p] planar
__device__ __nv_bfloat16 g_dwb[4 * 9 * 9216];       // [i][k][hi 64x72 | lo 64x72]
__device__ __nv_bfloat16 g_owb[4 * 9 * 4608];       // [j][k][hi 32x72 | lo 32x72]
__device__ float g_cat[4 * BN * CN * HWN];          // [i][b][o][p]
__device__ float g_bsums[4 * BN * 64 * 64];         // [i][b][rowpair][o]
__device__ float g_bsum2[1024];                     // [(i*4+b)*64+o]
__device__ float g_gate[BN * 256];                  // 1 + sigmoid(...)

__device__ __forceinline__ ull pack2(float a, float b) {
    ull r;
    asm("mov.b64 %0, {%1, %2};" : "=l"(r) : "f"(a), "f"(b));
    return r;
}
__device__ __forceinline__ void ffma2(ull& d, ull a, ull b) {
    asm("fma.rn.f32x2 %0, %1, %2, %0;" : "+l"(d) : "l"(a), "l"(b));
}
// split packed f32 pair (fx -> lower half, fy -> upper half) into bf16x2 hi + lo residual
__device__ __forceinline__ void bf16_split(float fx, float fy, unsigned& h, unsigned& l) {
    asm("cvt.rn.bf16x2.f32 %0, %1, %2;" : "=r"(h) : "f"(fy), "f"(fx));
    float hy = __uint_as_float(h & 0xFFFF0000u);
    float hx = __uint_as_float(h << 16);
    float ly = fy - hy, lx = fx - hx;
    asm("cvt.rn.bf16x2.f32 %0, %1, %2;" : "=r"(l) : "f"(ly), "f"(lx));
}

// ---------------- K1: NCHW -> NHWC transpose of x (+ bf16 hi/lo planes) ----------------
__global__ void transpose_kernel(const float* __restrict__ x) {
    __shared__ float tile[32][33];
    int b  = blockIdx.z;
    int p0 = blockIdx.x * 32;
    int c0 = blockIdx.y * 32;
    for (int i = threadIdx.y; i < 32; i += 8)
        tile[i][threadIdx.x] = x[(b * 64 + c0 + i) * HWN + p0 + threadIdx.x];
    __syncthreads();
    for (int i = threadIdx.y; i < 32; i += 8) {
        float v = tile[threadIdx.x][i];
        size_t o = (size_t)(b * HWN + p0 + i) * 64 + c0 + threadIdx.x;
        g_xhwc[o] = v;
        __nv_bfloat16 h = __float2bfloat16(v);
        g_xbf_hi[o] = h;
        g_xbf_lo[o] = __float2bfloat16(v - __bfloat162float(h));
    }
}

// ---------------- K1b: dw -> bf16 hi/lo A tiles [o][c], pitch 72 ----------------
__global__ void dwb_kernel(const float* __restrict__ dw) {
    int idx = blockIdx.x * 256 + threadIdx.x;  // < 73728
    int i  = idx / 18432;
    int r  = idx % 18432;
    int k  = r / 2048;
    int r2 = r % 2048;
    int o  = r2 >> 5;
    int e  = r2 & 31;
    int c  = e * 2;
    float v0 = dw[((i * 64 + o) * 64 + c) * 9 + k];
    float v1 = dw[((i * 64 + o) * 64 + c + 1) * 9 + k];
    unsigned h, l;
    bf16_split(v0, v1, h, l);
    __nv_bfloat16* base = g_dwb + (size_t)(i * 9 + k) * 9216;
    *(unsigned*)(base + o * 72 + c)        = h;
    *(unsigned*)(base + 4608 + o * 72 + c) = l;
}

// ---------------- K1c: ow -> bf16 hi/lo A tiles [32(pad 18)][64], pitch 72 ----------------
__global__ void owb_kernel(const float* __restrict__ ow) {
    int idx = blockIdx.x * 256 + threadIdx.x;  // < 73728
    int j  = idx / 18432;
    int r  = idx % 18432;
    int k  = r / 2048;
    int r2 = r % 2048;
    int o  = r2 >> 6;
    int c  = r2 & 63;
    float v = (o < 18) ? ow[((j * 18 + o) * 64 + c) * 9 + k] : 0.f;
    __nv_bfloat16 h = __float2bfloat16(v);
    __nv_bfloat16* base = g_owb + (size_t)(j * 9 + k) * 4608;
    base[o * 72 + c]        = h;
    base[2304 + o * 72 + c] = __float2bfloat16(v - __bfloat162float(h));
}

// ---------------- K2: offset conv via WMMA, 2 rows (256 px) per block ----------------
#define OPIT 72
#define OB_ELEMS (256 * OPIT)                  // one plane
#define OSMEM ((2 * OB_ELEMS + 2 * 2304) * 2)  // 82944 B
__global__ __launch_bounds__(256, 2) void offsetw_kernel(const float* __restrict__ ob) {
    extern __shared__ __nv_bfloat16 osb[];
    __nv_bfloat16* Bhs = osb;
    __nv_bfloat16* Bls = osb + OB_ELEMS;
    __nv_bfloat16* Aos = osb + 2 * OB_ELEMS;   // hi at 0, lo at 2304

    int rp = blockIdx.x, b = blockIdx.y, j = blockIdx.z;
    int p0 = rp * 256;
    int rate = c_RATES[j];
    int tid = threadIdx.x;
    int warp = tid >> 5;
    int otile = warp & 1;
    int pxq = warp >> 1;          // 4 quarters x 64 px

    wmma::fragment<wmma::accumulator, 16, 16, 16, float> acc[4];
#pragma unroll
    for (int nt = 0; nt < 4; nt++) wmma::fill_fragment(acc[nt], 0.f);

    int lane8 = tid & 7;
    int cbase = lane8 * 8;

    for (int k = 0; k < 9; k++) {
        __syncthreads();
        // stage A tap (4608 elems = 576 uint4)
        {
            const uint4* src = (const uint4*)(g_owb + (size_t)(j * 9 + k) * 4608);
            uint4* dst = (uint4*)Aos;
            dst[tid] = src[tid];
            dst[tid + 256] = src[tid + 256];
            if (tid < 64) dst[tid + 512] = src[tid + 512];
        }
        // stage shifted window: 8 passes x 32 px (full-line LDG)
        {
            int kyr = (k / 3 - 1) * rate;
            int xsh = (k % 3 - 1) * rate;
#pragma unroll
            for (int pass = 0; pass < 8; pass++) {
                int px = pass * 32 + (tid >> 3);
                int srow = rp * 2 + (px >> 7) + kyr;
                int sx = (px & 127) + xsh;
                bool v = ((unsigned)srow < HH) && ((unsigned)sx < WW);
                uint4 vh = make_uint4(0, 0, 0, 0), vl = make_uint4(0, 0, 0, 0);
                if (v) {
                    size_t src = ((size_t)b * HWN + srow * WW + sx) * 64 + cbase;
                    vh = *(const uint4*)(g_xbf_hi + src);
                    vl = *(const uint4*)(g_xbf_lo + src);
                }
                *(uint4*)(Bhs + px * OPIT + cbase) = vh;
                *(uint4*)(Bls + px * OPIT + cbase) = vl;
            }
        }
        __syncthreads();

#pragma unroll
        for (int kc = 0; kc < 4; kc++) {
            wmma::fragment<wmma::matrix_a, 16, 16, 16, __nv_bfloat16, wmma::row_major> Ah, Al;
            wmma::load_matrix_sync(Ah, Aos + otile * 16 * OPIT + kc * 16, OPIT);
            wmma::load_matrix_sync(Al, Aos + 2304 + otile * 16 * OPIT + kc * 16, OPIT);
#pragma unroll
            for (int nt = 0; nt < 4; nt++) {
                wmma::fragment<wmma::matrix_b, 16, 16, 16, __nv_bfloat16, wmma::col_major> Bh, Bl;
                int pxb = pxq * 64 + nt * 16;
                wmma::load_matrix_sync(Bh, Bhs + pxb * OPIT + kc * 16, OPIT);
                wmma::load_matrix_sync(Bl, Bls + pxb * OPIT + kc * 16, OPIT);
                wmma::mma_sync(acc[nt], Ah, Bh, acc[nt]);
                wmma::mma_sync(acc[nt], Ah, Bl, acc[nt]);
                wmma::mma_sync(acc[nt], Al, Bh, acc[nt]);
            }
        }
    }

    // epilogue: frags -> smem (32 x 260 f32), then bias+relu scatter to planar g_off
    __syncthreads();
    float* osm = (float*)osb;
#pragma unroll
    for (int nt = 0; nt < 4; nt++)
        wmma::store_matrix_sync(osm + (otile * 16) * 260 + pxq * 64 + nt * 16,
                                acc[nt], 260, wmma::mem_row_major);
    __syncthreads();
    for (int idx = tid; idx < 18 * 256; idx += 256) {
        int k2 = idx >> 8, px = idx & 255;
        g_off[(size_t)(j * 18 + k2) * BHW + b * HWN + p0 + px] =
            fmaxf(osm[k2 * 260 + px] + ob[j * 18 + k2], 0.f);
    }
}

// ---------------- K3: gather + WMMA GEMM, 2 rows (256 px) per block ----------------
#define SPIT 72
#define SB_ELEMS (256 * SPIT)
#define AB_ELEMS (64 * SPIT)
#define BSMEM ((2 * SB_ELEMS + 2 * AB_ELEMS) * 2)  // 92160 B
__global__ __launch_bounds__(256, 2) void branch_kernel() {
    extern __shared__ __nv_bfloat16 bsm[];
    __nv_bfloat16* Shi = bsm;
    __nv_bfloat16* Slo = bsm + SB_ELEMS;
    __nv_bfloat16* Ash = bsm + 2 * SB_ELEMS;   // hi at 0, lo at AB_ELEMS

    int i = blockIdx.z, b = blockIdx.y, rp = blockIdx.x;
    int p0 = rp * 256;
    int j = (i + 3) & 3;
    int rate = c_RATES[i];
    int tid = threadIdx.x;
    int warp = tid >> 5;
    int otile = warp & 3, ph = warp >> 2;   // ph covers 128 px
    int lane8 = tid & 7;
    int ca = lane8 * 4;

    const float* xb   = &g_xhwc[b * HWN * 64];
    const float* offb = g_off + j * 18 * BHW + b * HWN + p0;

    wmma::fragment<wmma::accumulator, 16, 16, 16, float> acc[8];
#pragma unroll
    for (int nt = 0; nt < 8; nt++) wmma::fill_fragment(acc[nt], 0.f);

    for (int k = 0; k < 9; k++) {
        __syncthreads();
        // stage A tap (9216 elems = 1152 uint4)
        {
            const uint4* src = (const uint4*)(g_dwb + (size_t)(i * 9 + k) * 9216);
            uint4* dst = (uint4*)Ash;
            dst[tid]        = src[tid];
            dst[tid + 256]  = src[tid + 256];
            dst[tid + 512]  = src[tid + 512];
            dst[tid + 768]  = src[tid + 768];
            if (tid < 128) dst[tid + 1024] = src[tid + 1024];
        }
        // gather tap k: 8 passes x 32 px (full-line LDG, bf16 split)
        int kyr = (k / 3 - 1) * rate;
        int kxr = (k % 3 - 1) * rate;
        const float* offY = offb + (2 * k) * BHW;
        const float* offX = offb + (2 * k + 1) * BHW;
#pragma unroll 2
        for (int pass = 0; pass < 8; pass++) {
            int sp = pass * 32 + (tid >> 3);
            int myY = rp * 2 + (sp >> 7);
            int myX = sp & 127;
            float dy = __ldg(offY + sp);
            float dx = __ldg(offX + sp);
            float py = (float)(myY + kyr) + dy;
            float px = (float)(myX + kxr) + dx;
            float fy = floorf(py), fx = floorf(px);
            int iy0 = (int)fy, ix0 = (int)fx;
            float wy1 = py - fy, wx1 = px - fx;
            float wy0 = 1.f - wy1, wx0 = 1.f - wx1;
            bool vy0 = (unsigned)iy0 < HH, vy1 = (unsigned)(iy0 + 1) < HH;
            bool vx0 = (unsigned)ix0 < WW, vx1 = (unsigned)(ix0 + 1) < WW;
            float w00 = (vy0 && vx0) ? wy0 * wx0 : 0.f;
            float w01 = (vy0 && vx1) ? wy0 * wx1 : 0.f;
            float w10 = (vy1 && vx0) ? wy1 * wx0 : 0.f;
            float w11 = (vy1 && vx1) ? wy1 * wx1 : 0.f;
            ull w00d = pack2(w00, w00), w01d = pack2(w01, w01);
            ull w10d = pack2(w10, w10), w11d = pack2(w11, w11);
            int cy0 = min(max(iy0, 0), HH - 1), cy1 = min(max(iy0 + 1, 0), HH - 1);
            int cx0 = min(max(ix0, 0), WW - 1), cx1 = min(max(ix0 + 1, 0), WW - 1);
            const float* b00 = xb + (cy0 * WW + cx0) * 64;
            const float* b01 = xb + (cy0 * WW + cx1) * 64;
            const float* b10 = xb + (cy1 * WW + cx0) * 64;
            const float* b11 = xb + (cy1 * WW + cx1) * 64;
#pragma unroll
            for (int half = 0; half < 2; half++) {
                int cc = ca + half * 32;
                ulonglong2 t00 = *(const ulonglong2*)(b00 + cc);
                ulonglong2 t01 = *(const ulonglong2*)(b01 + cc);
                ulonglong2 t10 = *(const ulonglong2*)(b10 + cc);
                ulonglong2 t11 = *(const ulonglong2*)(b11 + cc);
                ull r0 = 0, r1 = 0;
                ffma2(r0, w00d, t00.x); ffma2(r1, w00d, t00.y);
                ffma2(r0, w01d, t01.x); ffma2(r1, w01d, t01.y);
                ffma2(r0, w10d, t10.x); ffma2(r1, w10d, t10.y);
                ffma2(r0, w11d, t11.x); ffma2(r1, w11d, t11.y);
                float2 f0 = *(float2*)&r0, f1 = *(float2*)&r1;
                unsigned h0, l0, h1, l1;
                bf16_split(f0.x, f0.y, h0, l0);
                bf16_split(f1.x, f1.y, h1, l1);
                unsigned* dh = (unsigned*)(Shi + sp * SPIT + cc);
                dh[0] = h0; dh[1] = h1;
                unsigned* dl = (unsigned*)(Slo + sp * SPIT + cc);
                dl[0] = l0; dl[1] = l1;
            }
        }
        __syncthreads();

#pragma unroll
        for (int kc = 0; kc < 4; kc++) {
            wmma::fragment<wmma::matrix_a, 16, 16, 16, __nv_bfloat16, wmma::row_major> Ah, Al;
            wmma::load_matrix_sync(Ah, Ash + otile * 16 * SPIT + kc * 16, SPIT);
            wmma::load_matrix_sync(Al, Ash + AB_ELEMS + otile * 16 * SPIT + kc * 16, SPIT);
#pragma unroll
            for (int nt = 0; nt < 8; nt++) {
                wmma::fragment<wmma::matrix_b, 16, 16, 16, __nv_bfloat16, wmma::col_major> Bh, Bl;
                int pxb = ph * 128 + nt * 16;
                wmma::load_matrix_sync(Bh, Shi + pxb * SPIT + kc * 16, SPIT);
                wmma::load_matrix_sync(Bl, Slo + pxb * SPIT + kc * 16, SPIT);
                wmma::mma_sync(acc[nt], Ah, Bh, acc[nt]);
                wmma::mma_sync(acc[nt], Ah, Bl, acc[nt]);
                wmma::mma_sync(acc[nt], Al, Bh, acc[nt]);
            }
        }
    }

    // ---- epilogue: frags -> smem (64 x 260 f32) -> coalesced g_cat + per-o sums ----
    __syncthreads();
    float* osm = (float*)bsm;
#pragma unroll
    for (int nt = 0; nt < 8; nt++)
        wmma::store_matrix_sync(osm + (otile * 16) * 260 + ph * 128 + nt * 16,
                                acc[nt], 260, wmma::mem_row_major);
    __syncthreads();
    float* outp = &g_cat[((i * 4 + b) * 64) * HWN];
    for (int idx = tid; idx < 64 * 64; idx += 256) {
        int o = idx >> 6, q = idx & 63;
        *(float4*)&outp[o * HWN + p0 + q * 4] = *(float4*)&osm[o * 260 + q * 4];
    }
    {
        int o = tid >> 2, q = tid & 3;
        float s = 0.f;
#pragma unroll
        for (int t = 0; t < 64; t++) s += osm[o * 260 + q * 64 + t];
        s += __shfl_xor_sync(0xffffffff, s, 1);
        s += __shfl_xor_sync(0xffffffff, s, 2);
        if (q == 0) g_bsums[((i * 4 + b) * 64 + rp) * 64 + o] = s;
    }
}

// ---------------- K3b: collapse g_bsums rows -> g_bsum2 ----------------
__global__ void bsum_reduce() {
    int idx = blockIdx.x * 256 + threadIdx.x;  // 0..1023
    int ib = idx >> 6, o = idx & 63;
    float s = 0.f;
    for (int r = 0; r < 64; r++)
        s += g_bsums[(ib * 64 + r) * 64 + o];
    g_bsum2[idx] = s;
}

// ---------------- K4: SE MLP (tiny, one block) ----------------
__global__ void se_kernel(const float* __restrict__ w1, const float* __restrict__ b1,
                          const float* __restrict__ w2, const float* __restrict__ b2) {
    __shared__ float gm[4 * 256];
    __shared__ float h1[4 * 64];
    int tid = threadIdx.x;  // 256
    for (int idx = tid; idx < 1024; idx += 256) {
        int b = idx >> 8, ch = idx & 255;
        gm[b * 256 + ch] = g_bsum2[((ch >> 6) * 4 + b) * 64 + (ch & 63)] * (1.f / 16384.f);
    }
    __syncthreads();
    {
        int b = tid >> 6, oc = tid & 63;
        float a = b1[oc];
        for (int ch = 0; ch < 256; ch++) a += w1[oc * 256 + ch] * gm[b * 256 + ch];
        h1[b * 64 + oc] = fmaxf(a, 0.f);
    }
    __syncthreads();
    for (int idx = tid; idx < 1024; idx += 256) {
        int b = idx >> 8, ch = idx & 255;
        float a = b2[ch];
        for (int oc = 0; oc < 64; oc++) a += w2[ch * 64 + oc] * h1[b * 64 + oc];
        g_gate[b * 256 + ch] = 1.f + 1.f / (1.f + expf(-a));
    }
}

// ---------------- K5: gated fuse + residual ----------------
__global__ void final_kernel(const float* __restrict__ x, float* __restrict__ out) {
    int idx = blockIdx.x * 256 + threadIdx.x;  // < 1048576 float4s
    int p4 = idx & 4095;
    int o  = (idx >> 12) & 63;
    int b  = idx >> 18;
    float4 a = ((const float4*)x)[idx];
#pragma unroll
    for (int i = 0; i < 4; i++) {
        float g = g_gate[b * 256 + i * 64 + o];
        float4 cv = ((const float4*)g_cat)[((i * 4 + b) * 64 + o) * 4096 + p4];
        a.x += g * cv.x;
        a.y += g * cv.y;
        a.z += g * cv.z;
        a.w += g * cv.w;
    }
    ((float4*)out)[idx] = a;
}

extern "C" void kernel_launch(void* const* d_in, const int* in_sizes, int n_in,
                              void* d_out, int out_size) {
    const float* x  = (const float*)d_in[0];
    const float* dw = (const float*)d_in[1];
    const float* ow = (const float*)d_in[2];
    const float* ob = (const float*)d_in[3];
    const float* w1 = (const float*)d_in[4];
    const float* b1 = (const float*)d_in[5];
    const float* w2 = (const float*)d_in[6];
    const float* b2 = (const float*)d_in[7];
    float* out = (float*)d_out;

    cudaFuncSetAttribute(offsetw_kernel, cudaFuncAttributeMaxDynamicSharedMemorySize, OSMEM);
    cudaFuncSetAttribute(branch_kernel, cudaFuncAttributeMaxDynamicSharedMemorySize, BSMEM);

    transpose_kernel<<<dim3(512, 2, 4), dim3(32, 8)>>>(x);
    dwb_kernel<<<288, 256>>>(dw);
    owb_kernel<<<288, 256>>>(ow);
    offsetw_kernel<<<dim3(64, 4, 4), 256, OSMEM>>>(ob);
    branch_kernel<<<dim3(64, 4, 4), 256, BSMEM>>>();
    bsum_reduce<<<4, 256>>>();
    se_kernel<<<1, 256>>>(w1, b1, w2, b2);
    final_kernel<<<4096, 256>>>(x, out);
}

// round 17
// speedup vs baseline: 1.0626x; 1.0626x over previous
#include <cuda_runtime.h>
#include <cuda_bf16.h>
#include <mma.h>
#include <cstdint>

using namespace nvcuda;

#define HH 128
#define WW 128
#define HWN 16384
#define BHW (4 * 16384)
#define BN 4
#define CN 64

typedef unsigned long long ull;

__device__ __constant__ int c_RATES[4] = {2, 3, 5, 9};

// Scratch (static device globals: allocation-free, graph-capturable)
__device__ float g_xhwc[BN * HWN * CN];             // [b][p][c] f32
__device__ __nv_bfloat16 g_xbf_hi[BN * HWN * CN];   // [b][p][c] bf16 hi
__device__ __nv_bfloat16 g_xbf_lo[BN * HWN * CN];   // [b][p][c] bf16 lo residual
__device__ float g_off[4 * 18 * BHW];               // [j][k2][b*HW+p] planar
__device__ __nv_bfloat16 g_dwb[4 * 9 * 9216];       // [i][k][hi 64x72 | lo 64x72]
__device__ __nv_bfloat16 g_owb[4 * 9 * 4608];       // [j][k][hi 32x72 | lo 32x72]
__device__ float g_cat[4 * BN * CN * HWN];          // [i][b][o][p]
__device__ float g_bsums[4 * BN * 128 * 64];        // [i][b][row][o]
__device__ float g_bsum2[1024];                     // [(i*4+b)*64+o]
__device__ float g_gate[BN * 256];                  // 1 + sigmoid(...)

__device__ __forceinline__ ull pack2(float a, float b) {
    ull r;
    asm("mov.b64 %0, {%1, %2};" : "=l"(r) : "f"(a), "f"(b));
    return r;
}
__device__ __forceinline__ void ffma2(ull& d, ull a, ull b) {
    asm("fma.rn.f32x2 %0, %1, %2, %0;" : "+l"(d) : "l"(a), "l"(b));
}
// split packed f32 pair (fx -> lower half, fy -> upper half) into bf16x2 hi + lo residual
__device__ __forceinline__ void bf16_split(float fx, float fy, unsigned& h, unsigned& l) {
    asm("cvt.rn.bf16x2.f32 %0, %1, %2;" : "=r"(h) : "f"(fy), "f"(fx));
    float hy = __uint_as_float(h & 0xFFFF0000u);
    float hx = __uint_as_float(h << 16);
    float ly = fy - hy, lx = fx - hx;
    asm("cvt.rn.bf16x2.f32 %0, %1, %2;" : "=r"(l) : "f"(ly), "f"(lx));
}

// ---------------- K1: NCHW -> NHWC transpose of x (+ bf16 hi/lo planes) ----------------
__global__ void transpose_kernel(const float* __restrict__ x) {
    __shared__ float tile[32][33];
    int b  = blockIdx.z;
    int p0 = blockIdx.x * 32;
    int c0 = blockIdx.y * 32;
    for (int i = threadIdx.y; i < 32; i += 8)
        tile[i][threadIdx.x] = x[(b * 64 + c0 + i) * HWN + p0 + threadIdx.x];
    __syncthreads();
    for (int i = threadIdx.y; i < 32; i += 8) {
        float v = tile[threadIdx.x][i];
        size_t o = (size_t)(b * HWN + p0 + i) * 64 + c0 + threadIdx.x;
        g_xhwc[o] = v;
        __nv_bfloat16 h = __float2bfloat16(v);
        g_xbf_hi[o] = h;
        g_xbf_lo[o] = __float2bfloat16(v - __bfloat162float(h));
    }
}

// ---------------- K1b: dw -> bf16 hi/lo A tiles [o][c], pitch 72 ----------------
__global__ void dwb_kernel(const float* __restrict__ dw) {
    int idx = blockIdx.x * 256 + threadIdx.x;  // < 73728
    int i  = idx / 18432;
    int r  = idx % 18432;
    int k  = r / 2048;
    int r2 = r % 2048;
    int o  = r2 >> 5;
    int e  = r2 & 31;
    int c  = e * 2;
    float v0 = dw[((i * 64 + o) * 64 + c) * 9 + k];
    float v1 = dw[((i * 64 + o) * 64 + c + 1) * 9 + k];
    unsigned h, l;
    bf16_split(v0, v1, h, l);
    __nv_bfloat16* base = g_dwb + (size_t)(i * 9 + k) * 9216;
    *(unsigned*)(base + o * 72 + c)        = h;
    *(unsigned*)(base + 4608 + o * 72 + c) = l;
}

// ---------------- K1c: ow -> bf16 hi/lo A tiles [32(pad 18)][64], pitch 72 ----------------
__global__ void owb_kernel(const float* __restrict__ ow) {
    int idx = blockIdx.x * 256 + threadIdx.x;  // < 73728
    int j  = idx / 18432;
    int r  = idx % 18432;
    int k  = r / 2048;
    int r2 = r % 2048;
    int o  = r2 >> 6;
    int c  = r2 & 63;
    float v = (o < 18) ? ow[((j * 18 + o) * 64 + c) * 9 + k] : 0.f;
    __nv_bfloat16 h = __float2bfloat16(v);
    __nv_bfloat16* base = g_owb + (size_t)(j * 9 + k) * 4608;
    base[o * 72 + c]        = h;
    base[2304 + o * 72 + c] = __float2bfloat16(v - __bfloat162float(h));
}

// ---------------- K2: offset conv via WMMA (bf16 split, A staged in smem) ----------------
#define OPIT 72
__global__ __launch_bounds__(256) void offsetw_kernel(const float* __restrict__ ob) {
    __shared__ __nv_bfloat16 SB[2 * 128 * OPIT + 4608];  // Bh | Bl | A(hi+lo)
    __nv_bfloat16* Bhs = SB;
    __nv_bfloat16* Bls = SB + 128 * OPIT;
    __nv_bfloat16* Aos = SB + 2 * 128 * OPIT;  // hi at 0, lo at 2304

    int row = blockIdx.x, b = blockIdx.y, j = blockIdx.z;
    int p0 = row * 128;
    int rate = c_RATES[j];
    int tid = threadIdx.x;
    int warp = tid >> 5;
    int otile = warp & 1;
    int pxq = warp >> 1;

    wmma::fragment<wmma::accumulator, 16, 16, 16, float> acc[2];
    wmma::fill_fragment(acc[0], 0.f);
    wmma::fill_fragment(acc[1], 0.f);

    int lane8 = tid & 7;
    int cbase = lane8 * 8;

    for (int k = 0; k < 9; k++) {
        __syncthreads();
        // stage A tap (4608 elems = 576 uint4)
        {
            const uint4* src = (const uint4*)(g_owb + (size_t)(j * 9 + k) * 4608);
            uint4* dst = (uint4*)Aos;
            dst[tid] = src[tid];
            dst[tid + 256] = src[tid + 256];
            if (tid < 64) dst[tid + 512] = src[tid + 512];
        }
        // stage shifted window (full-line LDG)
        {
            int srow = row + (k / 3 - 1) * rate;
            int xsh = (k % 3 - 1) * rate;
            bool vr = (unsigned)srow < HH;
#pragma unroll
            for (int pass = 0; pass < 4; pass++) {
                int px = pass * 32 + (tid >> 3);
                int sx = px + xsh;
                bool v = vr && ((unsigned)sx < WW);
                uint4 vh = make_uint4(0, 0, 0, 0), vl = make_uint4(0, 0, 0, 0);
                if (v) {
                    size_t src = ((size_t)b * HWN + srow * WW + sx) * 64 + cbase;
                    vh = *(const uint4*)(g_xbf_hi + src);
                    vl = *(const uint4*)(g_xbf_lo + src);
                }
                *(uint4*)(Bhs + px * OPIT + cbase) = vh;
                *(uint4*)(Bls + px * OPIT + cbase) = vl;
            }
        }
        __syncthreads();

#pragma unroll
        for (int kc = 0; kc < 4; kc++) {
            wmma::fragment<wmma::matrix_a, 16, 16, 16, __nv_bfloat16, wmma::row_major> Ah, Al;
            wmma::load_matrix_sync(Ah, Aos + otile * 16 * OPIT + kc * 16, OPIT);
            wmma::load_matrix_sync(Al, Aos + 2304 + otile * 16 * OPIT + kc * 16, OPIT);
#pragma unroll
            for (int nt = 0; nt < 2; nt++) {
                wmma::fragment<wmma::matrix_b, 16, 16, 16, __nv_bfloat16, wmma::col_major> Bh, Bl;
                int pxb = pxq * 32 + nt * 16;
                wmma::load_matrix_sync(Bh, Bhs + pxb * OPIT + kc * 16, OPIT);
                wmma::load_matrix_sync(Bl, Bls + pxb * OPIT + kc * 16, OPIT);
                wmma::mma_sync(acc[nt], Ah, Bh, acc[nt]);
                wmma::mma_sync(acc[nt], Ah, Bl, acc[nt]);
                wmma::mma_sync(acc[nt], Al, Bh, acc[nt]);
            }
        }
    }

    // epilogue: stage to smem, then bias+relu scatter to planar g_off
    __syncthreads();
    float* osm = (float*)SB;   // 32 x 132 pitch (16896 B)
#pragma unroll
    for (int nt = 0; nt < 2; nt++)
        wmma::store_matrix_sync(osm + (otile * 16) * 132 + pxq * 32 + nt * 16,
                                acc[nt], 132, wmma::mem_row_major);
    __syncthreads();
    for (int idx = tid; idx < 18 * 128; idx += 256) {
        int k2 = idx >> 7, px = idx & 127;
        g_off[(size_t)(j * 18 + k2) * BHW + b * HWN + p0 + px] =
            fmaxf(osm[k2 * 132 + px] + ob[j * 18 + k2], 0.f);
    }
}

// ---------------- K3: gather (bf16 split) + WMMA GEMM (A staged in smem) ----------------
// 8 warps = 4 o-tiles x 2 px-halves, acc[4]. Fused SE-sum epilogue.
#define SPIT 72
#define SBUF (128 * SPIT)
#define ABUF (64 * SPIT)
__global__ __launch_bounds__(256) void branch_kernel() {
    __shared__ __nv_bfloat16 SM[2 * SBUF + 2 * ABUF];  // Shi | Slo | Ahi | Alo (55296 B)
    __nv_bfloat16* Shi = SM;
    __nv_bfloat16* Slo = SM + SBUF;
    __nv_bfloat16* Ash = SM + 2 * SBUF;   // hi at 0, lo at ABUF

    int i = blockIdx.z, b = blockIdx.y, row = blockIdx.x;
    int p0 = row * 128;
    int j = (i + 3) & 3;
    int rate = c_RATES[i];
    int tid = threadIdx.x;
    int warp = tid >> 5;
    int otile = warp & 3, ph = warp >> 2;
    int lane8 = tid & 7;
    int ca = lane8 * 4;

    const float* xb   = &g_xhwc[b * HWN * 64];
    const float* offb = g_off + j * 18 * BHW + b * HWN + p0;

    wmma::fragment<wmma::accumulator, 16, 16, 16, float> acc[4];
#pragma unroll
    for (int nt = 0; nt < 4; nt++) wmma::fill_fragment(acc[nt], 0.f);

    for (int k = 0; k < 9; k++) {
        __syncthreads();
        // stage A tap (9216 elems = 1152 uint4)
        {
            const uint4* src = (const uint4*)(g_dwb + (size_t)(i * 9 + k) * 9216);
            uint4* dst = (uint4*)Ash;
            dst[tid]        = src[tid];
            dst[tid + 256]  = src[tid + 256];
            dst[tid + 512]  = src[tid + 512];
            dst[tid + 768]  = src[tid + 768];
            if (tid < 128) dst[tid + 1024] = src[tid + 1024];
        }
        // gather tap k (full-line LDG, bf16 split)
        int kyr = (k / 3 - 1) * rate;
        int kxr = (k % 3 - 1) * rate;
        const float* offY = offb + (2 * k) * BHW;
        const float* offX = offb + (2 * k + 1) * BHW;
#pragma unroll 2
        for (int pass = 0; pass < 4; pass++) {
            int sp = pass * 32 + (tid >> 3);
            float dy = __ldg(offY + sp);
            float dx = __ldg(offX + sp);
            float py = (float)(row + kyr) + dy;
            float px = (float)(sp + kxr) + dx;
            float fy = floorf(py), fx = floorf(px);
            int iy0 = (int)fy, ix0 = (int)fx;
            float wy1 = py - fy, wx1 = px - fx;
            float wy0 = 1.f - wy1, wx0 = 1.f - wx1;
            bool vy0 = (unsigned)iy0 < HH, vy1 = (unsigned)(iy0 + 1) < HH;
            bool vx0 = (unsigned)ix0 < WW, vx1 = (unsigned)(ix0 + 1) < WW;
            float w00 = (vy0 && vx0) ? wy0 * wx0 : 0.f;
            float w01 = (vy0 && vx1) ? wy0 * wx1 : 0.f;
            float w10 = (vy1 && vx0) ? wy1 * wx0 : 0.f;
            float w11 = (vy1 && vx1) ? wy1 * wx1 : 0.f;
            ull w00d = pack2(w00, w00), w01d = pack2(w01, w01);
            ull w10d = pack2(w10, w10), w11d = pack2(w11, w11);
            int cy0 = min(max(iy0, 0), HH - 1), cy1 = min(max(iy0 + 1, 0), HH - 1);
            int cx0 = min(max(ix0, 0), WW - 1), cx1 = min(max(ix0 + 1, 0), WW - 1);
            const float* b00 = xb + (cy0 * WW + cx0) * 64;
            const float* b01 = xb + (cy0 * WW + cx1) * 64;
            const float* b10 = xb + (cy1 * WW + cx0) * 64;
            const float* b11 = xb + (cy1 * WW + cx1) * 64;
#pragma unroll
            for (int half = 0; half < 2; half++) {
                int cc = ca + half * 32;
                ulonglong2 t00 = *(const ulonglong2*)(b00 + cc);
                ulonglong2 t01 = *(const ulonglong2*)(b01 + cc);
                ulonglong2 t10 = *(const ulonglong2*)(b10 + cc);
                ulonglong2 t11 = *(const ulonglong2*)(b11 + cc);
                ull r0 = 0, r1 = 0;
                ffma2(r0, w00d, t00.x); ffma2(r1, w00d, t00.y);
                ffma2(r0, w01d, t01.x); ffma2(r1, w01d, t01.y);
                ffma2(r0, w10d, t10.x); ffma2(r1, w10d, t10.y);
                ffma2(r0, w11d, t11.x); ffma2(r1, w11d, t11.y);
                float2 f0 = *(float2*)&r0, f1 = *(float2*)&r1;
                unsigned h0, l0, h1, l1;
                bf16_split(f0.x, f0.y, h0, l0);
                bf16_split(f1.x, f1.y, h1, l1);
                unsigned* dh = (unsigned*)(Shi + sp * SPIT + cc);
                dh[0] = h0; dh[1] = h1;
                unsigned* dl = (unsigned*)(Slo + sp * SPIT + cc);
                dl[0] = l0; dl[1] = l1;
            }
        }
        __syncthreads();

#pragma unroll
        for (int kc = 0; kc < 4; kc++) {
            wmma::fragment<wmma::matrix_a, 16, 16, 16, __nv_bfloat16, wmma::row_major> Ah, Al;
            wmma::load_matrix_sync(Ah, Ash + otile * 16 * SPIT + kc * 16, SPIT);
            wmma::load_matrix_sync(Al, Ash + ABUF + otile * 16 * SPIT + kc * 16, SPIT);
#pragma unroll
            for (int nt = 0; nt < 4; nt++) {
                wmma::fragment<wmma::matrix_b, 16, 16, 16, __nv_bfloat16, wmma::col_major> Bh, Bl;
                int pxb = ph * 64 + nt * 16;
                wmma::load_matrix_sync(Bh, Shi + pxb * SPIT + kc * 16, SPIT);
                wmma::load_matrix_sync(Bl, Slo + pxb * SPIT + kc * 16, SPIT);
                wmma::mma_sync(acc[nt], Ah, Bh, acc[nt]);
                wmma::mma_sync(acc[nt], Ah, Bl, acc[nt]);
                wmma::mma_sync(acc[nt], Al, Bh, acc[nt]);
            }
        }
    }

    // ---- epilogue: frags -> smem -> coalesced g_cat + per-o partial sums ----
    __syncthreads();
    float* osm = (float*)SM;  // 64 x 132 f32 = 33792 B (fits in 55296 B)
#pragma unroll
    for (int nt = 0; nt < 4; nt++)
        wmma::store_matrix_sync(osm + (otile * 16) * 132 + ph * 64 + nt * 16,
                                acc[nt], 132, wmma::mem_row_major);
    __syncthreads();
    float* outp = &g_cat[((i * 4 + b) * 64) * HWN];
    for (int idx = tid; idx < 64 * 32; idx += 256) {
        int o = idx >> 5, q = idx & 31;
        *(float4*)&outp[o * HWN + p0 + q * 4] = *(float4*)&osm[o * 132 + q * 4];
    }
    {
        int o = tid >> 2, q = tid & 3;
        float s = 0.f;
#pragma unroll
        for (int t = 0; t < 32; t++) s += osm[o * 132 + q * 32 + t];
        s += __shfl_xor_sync(0xffffffff, s, 1);
        s += __shfl_xor_sync(0xffffffff, s, 2);
        if (q == 0) g_bsums[((i * 4 + b) * 128 + row) * 64 + o] = s;
    }
}

// ---------------- K3b: collapse g_bsums rows -> g_bsum2 ----------------
__global__ void bsum_reduce() {
    int idx = blockIdx.x * 256 + threadIdx.x;  // 0..1023
    int ib = idx >> 6, o = idx & 63;
    float s = 0.f;
    for (int r = 0; r < 128; r++)
        s += g_bsums[(ib * 128 + r) * 64 + o];
    g_bsum2[idx] = s;
}

// ---------------- K4: SE MLP (tiny, one block) ----------------
__global__ void se_kernel(const float* __restrict__ w1, const float* __restrict__ b1,
                          const float* __restrict__ w2, const float* __restrict__ b2) {
    __shared__ float gm[4 * 256];
    __shared__ float h1[4 * 64];
    int tid = threadIdx.x;  // 256
    for (int idx = tid; idx < 1024; idx += 256) {
        int b = idx >> 8, ch = idx & 255;
        gm[b * 256 + ch] = g_bsum2[((ch >> 6) * 4 + b) * 64 + (ch & 63)] * (1.f / 16384.f);
    }
    __syncthreads();
    {
        int b = tid >> 6, oc = tid & 63;
        float a = b1[oc];
        for (int ch = 0; ch < 256; ch++) a += w1[oc * 256 + ch] * gm[b * 256 + ch];
        h1[b * 64 + oc] = fmaxf(a, 0.f);
    }
    __syncthreads();
    for (int idx = tid; idx < 1024; idx += 256) {
        int b = idx >> 8, ch = idx & 255;
        float a = b2[ch];
        for (int oc = 0; oc < 64; oc++) a += w2[ch * 64 + oc] * h1[b * 64 + oc];
        g_gate[b * 256 + ch] = 1.f + 1.f / (1.f + expf(-a));
    }
}

// ---------------- K5: gated fuse + residual ----------------
__global__ void final_kernel(const float* __restrict__ x, float* __restrict__ out) {
    int idx = blockIdx.x * 256 + threadIdx.x;  // < 1048576 float4s
    int p4 = idx & 4095;
    int o  = (idx >> 12) & 63;
    int b  = idx >> 18;
    float4 a = ((const float4*)x)[idx];
#pragma unroll
    for (int i = 0; i < 4; i++) {
        float g = g_gate[b * 256 + i * 64 + o];
        float4 cv = ((const float4*)g_cat)[((i * 4 + b) * 64 + o) * 4096 + p4];
        a.x += g * cv.x;
        a.y += g * cv.y;
        a.z += g * cv.z;
        a.w += g * cv.w;
    }
    ((float4*)out)[idx] = a;
}

extern "C" void kernel_launch(void* const* d_in, const int* in_sizes, int n_in,
                              void* d_out, int out_size) {
    const float* x  = (const float*)d_in[0];
    const float* dw = (const float*)d_in[1];
    const float* ow = (const float*)d_in[2];
    const float* ob = (const float*)d_in[3];
    const float* w1 = (const float*)d_in[4];
    const float* b1 = (const float*)d_in[5];
    const float* w2 = (const float*)d_in[6];
    const float* b2 = (const float*)d_in[7];
    float* out = (float*)d_out;

    transpose_kernel<<<dim3(512, 2, 4), dim3(32, 8)>>>(x);
    dwb_kernel<<<288, 256>>>(dw);
    owb_kernel<<<288, 256>>>(ow);
    offsetw_kernel<<<dim3(128, 4, 4), 256>>>(ob);
    branch_kernel<<<dim3(128, 4, 4), 256>>>();
    bsum_reduce<<<4, 256>>>();
    se_kernel<<<1, 256>>>(w1, b1, w2, b2);
    final_kernel<<<4096, 256>>>(x, out);
}